// round 7
// baseline (speedup 1.0000x reference)
#include <cuda_runtime.h>

#define NN 100000
#define EMAX 1600000
#define SCAN_B 1024
#define SCAN_NB ((NN + SCAN_B - 1) / SCAN_B)   // 98

// ---- scratch (device globals; no runtime allocation allowed) ----
__device__ int      g_deg[NN];
__device__ int      g_off[NN + 1];
__device__ int      g_cur[NN];
__device__ int      g_csr[EMAX + NN];   // src node per CSR slot (sorted by dst)
__device__ float    g_h [NN * 64];      // transformed features for current layer
__device__ float    g_fb[NN * 64];      // layer-1 aggregated features
__device__ float    g_s [NN * 4];       // layer-0 aggregated scalars S[n][h]
__device__ float    g_es[NN * 4];       // per-node source attention logits
__device__ float    g_ed[NN * 4];       // per-node dest attention logits
__device__ unsigned g_gmax[12];         // per-layer per-head global max of es
__device__ unsigned g_xmm[2];           // [0]=enc(max x), [1]=enc(max -x)
__device__ int      g_bsum[SCAN_NB];
__device__ int      g_boff[SCAN_NB];

__device__ __forceinline__ unsigned fenc(float f) {
    unsigned u = __float_as_uint(f);
    return u ^ ((u & 0x80000000u) ? 0xFFFFFFFFu : 0x80000000u);
}
__device__ __forceinline__ float fdec(unsigned e) {
    unsigned u = e ^ ((e & 0x80000000u) ? 0x80000000u : 0xFFFFFFFFu);
    return __uint_as_float(u);
}
__device__ __forceinline__ float leaky02(float e) {
    return (e > 0.f) ? e : 0.2f * e;
}

// ------------------------------------------------------------------
// CSR construction
// ------------------------------------------------------------------
__global__ void k_init_deg() {
    int i = blockIdx.x * blockDim.x + threadIdx.x;
    if (i < NN) g_deg[i] = 1;           // self-loop
    if (i < 12) g_gmax[i] = 0u;
    if (i < 2)  g_xmm[i] = 0u;
}

__global__ void k_hist(const int* __restrict__ dst, int E) {
    int i = blockIdx.x * blockDim.x + threadIdx.x;
    if (i < E) atomicAdd(&g_deg[dst[i]], 1);
}

__global__ void k_scan1() {
    __shared__ int red[8];
    int b = blockIdx.x, t = threadIdx.x;
    int s = 0;
    #pragma unroll
    for (int j = 0; j < 4; j++) {
        int idx = b * SCAN_B + j * 256 + t;
        if (idx < NN) s += g_deg[idx];
    }
    #pragma unroll
    for (int o = 16; o >= 1; o >>= 1) s += __shfl_down_sync(0xffffffffu, s, o);
    if ((t & 31) == 0) red[t >> 5] = s;
    __syncthreads();
    if (t == 0) {
        int tot = 0;
        #pragma unroll
        for (int w = 0; w < 8; w++) tot += red[w];
        g_bsum[b] = tot;
    }
}

__global__ void k_scan2() {
    __shared__ int sh[128];
    int t = threadIdx.x;
    sh[t] = (t < SCAN_NB) ? g_bsum[t] : 0;
    __syncthreads();
    for (int o = 1; o < 128; o <<= 1) {
        int v = (t >= o) ? sh[t - o] : 0;
        __syncthreads();
        sh[t] += v;
        __syncthreads();
    }
    if (t < SCAN_NB) g_boff[t] = (t == 0) ? 0 : sh[t - 1];
    if (t == SCAN_NB - 1) g_off[NN] = sh[t];
}

__global__ void k_scan3() {
    __shared__ int sh[SCAN_B];
    int b = blockIdx.x, t = threadIdx.x;
    int i = b * SCAN_B + t;
    int v = (i < NN) ? g_deg[i] : 0;
    sh[t] = v;
    __syncthreads();
    for (int o = 1; o < SCAN_B; o <<= 1) {
        int u = (t >= o) ? sh[t - o] : 0;
        __syncthreads();
        sh[t] += u;
        __syncthreads();
    }
    if (i < NN) {
        int ex = sh[t] - v + g_boff[b];
        g_off[i] = ex;
        g_cur[i] = ex;
    }
}

__global__ void k_fill(const int* __restrict__ src, const int* __restrict__ dst, int E) {
    int i = blockIdx.x * blockDim.x + threadIdx.x;
    int tot = E + NN;
    if (i >= tot) return;
    int s, d;
    if (i < E) { s = src[i]; d = dst[i]; }
    else       { s = i - E; d = s; }
    int p = atomicAdd(&g_cur[d], 1);
    g_csr[p] = s;
}

// ------------------------------------------------------------------
// Global max/min of x (for layer-0 softmax bound)
// ------------------------------------------------------------------
__global__ void k_xmm(const float* __restrict__ x) {
    float mx = -1e30f, mn = 1e30f;
    for (int i = blockIdx.x * blockDim.x + threadIdx.x; i < NN;
         i += gridDim.x * blockDim.x) {
        float v = __ldg(x + i);
        mx = fmaxf(mx, v);
        mn = fminf(mn, v);
    }
    #pragma unroll
    for (int o = 16; o >= 1; o >>= 1) {
        mx = fmaxf(mx, __shfl_xor_sync(0xffffffffu, mx, o));
        mn = fminf(mn, __shfl_xor_sync(0xffffffffu, mn, o));
    }
    if ((threadIdx.x & 31) == 0) {
        atomicMax(&g_xmm[0], fenc(mx));
        atomicMax(&g_xmm[1], fenc(-mn));
    }
}

// ------------------------------------------------------------------
// Layer-0 aggregate, rank-1 specialization.
// h0[n,c] = x[n]*W0[c]  =>  out0 = S[n,h]*W0[c]+b0[c], S = sum alpha*x_src.
// Edge-parallel across lanes: one coalesced csr load + one 4B gather/edge.
// ------------------------------------------------------------------
__global__ __launch_bounds__(256) void k_agg0(
    const float* __restrict__ x,
    const float* __restrict__ W0,
    const float* __restrict__ as0,
    const float* __restrict__ ad0)
{
    __shared__ float ska[4], skd[4];
    int t = threadIdx.x;
    if (t < 8) ((float*)ska)[t] = 0.f;   // ska[0..3], skd[0..3] contiguous
    __syncthreads();
    if (t < 64) {
        float w = __ldg(W0 + t);
        atomicAdd(&ska[t >> 4], w * __ldg(as0 + t));
        atomicAdd(&skd[t >> 4], w * __ldg(ad0 + t));
    }
    __syncthreads();

    int lane = t & 31;
    int n = blockIdx.x * 8 + (t >> 5);
    if (n >= NN) return;

    float xmax = fdec(g_xmm[0]);
    float xmin = -fdec(g_xmm[1]);
    float xd = __ldg(x + n);

    float ka0 = ska[0], ka1 = ska[1], ka2 = ska[2], ka3 = ska[3];
    float kd0 = skd[0], kd1 = skd[1], kd2 = skd[2], kd3 = skd[3];
    // per-head upper bound on edge logits for this node
    float m0 = leaky02(fmaxf(ka0 * xmax, ka0 * xmin) + xd * kd0);
    float m1 = leaky02(fmaxf(ka1 * xmax, ka1 * xmin) + xd * kd1);
    float m2 = leaky02(fmaxf(ka2 * xmax, ka2 * xmin) + xd * kd2);
    float m3 = leaky02(fmaxf(ka3 * xmax, ka3 * xmin) + xd * kd3);
    float ed0v = xd * kd0, ed1v = xd * kd1, ed2v = xd * kd2, ed3v = xd * kd3;

    int beg = __ldg(&g_off[n]), end = __ldg(&g_off[n + 1]);
    float s0 = 0.f, s1 = 0.f, s2 = 0.f, s3 = 0.f;
    float a0 = 0.f, a1 = 0.f, a2 = 0.f, a3 = 0.f;
    for (int base = beg; base < end; base += 32) {
        int idx = base + lane;
        bool v = idx < end;
        int sc = __ldg(&g_csr[v ? idx : beg]);
        float xs = __ldg(x + sc);
        float w0 = v ? __expf(leaky02(xs * ka0 + ed0v) - m0) : 0.f;
        float w1 = v ? __expf(leaky02(xs * ka1 + ed1v) - m1) : 0.f;
        float w2 = v ? __expf(leaky02(xs * ka2 + ed2v) - m2) : 0.f;
        float w3 = v ? __expf(leaky02(xs * ka3 + ed3v) - m3) : 0.f;
        s0 += w0; s1 += w1; s2 += w2; s3 += w3;
        a0 += w0 * xs; a1 += w1 * xs; a2 += w2 * xs; a3 += w3 * xs;
    }
    #pragma unroll
    for (int o = 16; o >= 1; o >>= 1) {
        s0 += __shfl_xor_sync(0xffffffffu, s0, o);
        s1 += __shfl_xor_sync(0xffffffffu, s1, o);
        s2 += __shfl_xor_sync(0xffffffffu, s2, o);
        s3 += __shfl_xor_sync(0xffffffffu, s3, o);
        a0 += __shfl_xor_sync(0xffffffffu, a0, o);
        a1 += __shfl_xor_sync(0xffffffffu, a1, o);
        a2 += __shfl_xor_sync(0xffffffffu, a2, o);
        a3 += __shfl_xor_sync(0xffffffffu, a3, o);
    }
    if (lane == 0) {
        float4 S;
        S.x = a0 / (s0 + 1e-16f);
        S.y = a1 / (s1 + 1e-16f);
        S.z = a2 / (s2 + 1e-16f);
        S.w = a3 / (s3 + 1e-16f);
        *(float4*)(g_s + (size_t)n * 4) = S;
    }
}

// ------------------------------------------------------------------
// Transform layer 1, input reconstructed from S: out0[c]=S[h(c)]*W0[c]+b0[c].
// 4 nodes per warp, W smem loads hoisted.
// ------------------------------------------------------------------
__global__ __launch_bounds__(256) void k_transform_S(
    const float* __restrict__ W0g, const float* __restrict__ b0g,
    const float* __restrict__ Wg,
    const float* __restrict__ avs,
    const float* __restrict__ avd,
    int layer)
{
    __shared__ float Ws[64 * 64];
    __shared__ float As[64], Ad[64], W0s[64], B0s[64];
    __shared__ unsigned bmax[4];
    int t = threadIdx.x;
    for (int i = t; i < 64 * 64; i += blockDim.x) Ws[i] = Wg[i];
    if (t < 64) { As[t] = avs[t]; Ad[t] = avd[t]; W0s[t] = W0g[t]; B0s[t] = b0g[t]; }
    if (t < 4)  bmax[t] = 0u;
    __syncthreads();

    int lane = t & 31;
    int c0   = lane * 2;
    int n0 = blockIdx.x * 32 + (t >> 5) * 4;
    int nv = NN - n0; if (nv > 4) nv = 4;

    float4 Sv[4];
    #pragma unroll
    for (int r = 0; r < 4; r++)
        if (r < nv) Sv[r] = __ldg((const float4*)(g_s + (size_t)(n0 + r) * 4));

    float acc[4][2];
    #pragma unroll
    for (int r = 0; r < 4; r++) { acc[r][0] = 0.f; acc[r][1] = 0.f; }

    #pragma unroll
    for (int k = 0; k < 64; k += 4) {
        float2 w0 = *(const float2*)(Ws + (k + 0) * 64 + c0);
        float2 w1 = *(const float2*)(Ws + (k + 1) * 64 + c0);
        float2 w2 = *(const float2*)(Ws + (k + 2) * 64 + c0);
        float2 w3 = *(const float2*)(Ws + (k + 3) * 64 + c0);
        float4 wk = *(const float4*)(W0s + k);
        float4 bk = *(const float4*)(B0s + k);
        int hidx = k >> 4;
        #pragma unroll
        for (int r = 0; r < 4; r++) {
            if (r < nv) {
                float sh = (hidx == 0) ? Sv[r].x : (hidx == 1) ? Sv[r].y
                         : (hidx == 2) ? Sv[r].z : Sv[r].w;
                float xv0 = sh * wk.x + bk.x;
                float xv1 = sh * wk.y + bk.y;
                float xv2 = sh * wk.z + bk.z;
                float xv3 = sh * wk.w + bk.w;
                acc[r][0] += xv0 * w0.x; acc[r][1] += xv0 * w0.y;
                acc[r][0] += xv1 * w1.x; acc[r][1] += xv1 * w1.y;
                acc[r][0] += xv2 * w2.x; acc[r][1] += xv2 * w2.y;
                acc[r][0] += xv3 * w3.x; acc[r][1] += xv3 * w3.y;
            }
        }
    }

    #pragma unroll
    for (int r = 0; r < 4; r++) {
        if (r >= nv) break;
        int n = n0 + r;
        float a0 = acc[r][0], a1 = acc[r][1];
        size_t base = (size_t)n * 64 + c0;
        g_h[base]     = a0;
        g_h[base + 1] = a1;
        float ps = a0 * As[c0] + a1 * As[c0 + 1];
        float pd = a0 * Ad[c0] + a1 * Ad[c0 + 1];
        #pragma unroll
        for (int o = 4; o >= 1; o >>= 1) {
            ps += __shfl_down_sync(0xffffffffu, ps, o);
            pd += __shfl_down_sync(0xffffffffu, pd, o);
        }
        if ((lane & 7) == 0) {
            int hd = lane >> 3;
            g_es[n * 4 + hd] = ps;
            g_ed[n * 4 + hd] = pd;
            atomicMax(&bmax[hd], fenc(ps));
        }
    }
    __syncthreads();
    if (t < 4) atomicMax(&g_gmax[layer * 4 + t], bmax[t]);
}

// ------------------------------------------------------------------
// Transform (generic Fin=64), 4 nodes per warp, hoisted W loads.
// ------------------------------------------------------------------
__global__ __launch_bounds__(256) void k_transform(
    const float* __restrict__ xin,
    const float* __restrict__ Wg,
    const float* __restrict__ avs,
    const float* __restrict__ avd,
    int layer)
{
    __shared__ float Ws[64 * 64];
    __shared__ float As[64], Ad[64];
    __shared__ unsigned bmax[4];
    int t = threadIdx.x;
    for (int i = t; i < 64 * 64; i += blockDim.x) Ws[i] = Wg[i];
    if (t < 64) { As[t] = avs[t]; Ad[t] = avd[t]; }
    if (t < 4)  bmax[t] = 0u;
    __syncthreads();

    int lane = t & 31;
    int c0   = lane * 2;
    int n0 = blockIdx.x * 32 + (t >> 5) * 4;
    int nv = NN - n0; if (nv > 4) nv = 4;

    float acc[4][2];
    #pragma unroll
    for (int r = 0; r < 4; r++) { acc[r][0] = 0.f; acc[r][1] = 0.f; }

    const float* x0p = xin + (size_t)n0 * 64;
    #pragma unroll
    for (int k = 0; k < 64; k += 4) {
        float2 w0 = *(const float2*)(Ws + (k + 0) * 64 + c0);
        float2 w1 = *(const float2*)(Ws + (k + 1) * 64 + c0);
        float2 w2 = *(const float2*)(Ws + (k + 2) * 64 + c0);
        float2 w3 = *(const float2*)(Ws + (k + 3) * 64 + c0);
        #pragma unroll
        for (int r = 0; r < 4; r++) {
            if (r < nv) {
                float4 xv = __ldg((const float4*)(x0p + r * 64 + k));
                acc[r][0] += xv.x * w0.x; acc[r][1] += xv.x * w0.y;
                acc[r][0] += xv.y * w1.x; acc[r][1] += xv.y * w1.y;
                acc[r][0] += xv.z * w2.x; acc[r][1] += xv.z * w2.y;
                acc[r][0] += xv.w * w3.x; acc[r][1] += xv.w * w3.y;
            }
        }
    }

    #pragma unroll
    for (int r = 0; r < 4; r++) {
        if (r >= nv) break;
        int n = n0 + r;
        float a0 = acc[r][0], a1 = acc[r][1];
        size_t base = (size_t)n * 64 + c0;
        g_h[base]     = a0;
        g_h[base + 1] = a1;
        float ps = a0 * As[c0] + a1 * As[c0 + 1];
        float pd = a0 * Ad[c0] + a1 * Ad[c0 + 1];
        #pragma unroll
        for (int o = 4; o >= 1; o >>= 1) {
            ps += __shfl_down_sync(0xffffffffu, ps, o);
            pd += __shfl_down_sync(0xffffffffu, pd, o);
        }
        if ((lane & 7) == 0) {
            int hd = lane >> 3;
            g_es[n * 4 + hd] = ps;
            g_ed[n * 4 + hd] = pd;
            atomicMax(&bmax[hd], fenc(ps));
        }
    }
    __syncthreads();
    if (t < 4) atomicMax(&g_gmax[layer * 4 + t], bmax[t]);
}

// ------------------------------------------------------------------
// Single-pass softmax aggregation core (one warp per node).
// ------------------------------------------------------------------
__device__ __forceinline__ void agg_node(
    int n, int c0, int hd, int lane, int layer, const float* __restrict__ bias,
    float& o0, float& o1)
{
    int beg = __ldg(&g_off[n]), end = __ldg(&g_off[n + 1]);
    float edv = __ldg(&g_ed[n * 4 + hd]);
    float m = leaky02(fdec(g_gmax[layer * 4 + hd]) + edv);

    float s = 0.f, acc0 = 0.f, acc1 = 0.f;
    for (int base = beg; base < end; base += 32) {
        int rem = end - base;
        int cnt = rem < 32 ? rem : 32;
        int safel = lane < rem ? lane : 0;
        int myidx = __ldg(&g_csr[base + safel]);
        int j = 0;
        for (; j + 8 <= cnt; j += 8) {
            int sc[8]; float ev[8]; float2 hv[8];
            #pragma unroll
            for (int q = 0; q < 8; q++)
                sc[q] = __shfl_sync(0xffffffffu, myidx, j + q);
            #pragma unroll
            for (int q = 0; q < 8; q++) {
                ev[q] = __ldg(&g_es[sc[q] * 4 + hd]);
                hv[q] = __ldg((const float2*)(g_h + (size_t)sc[q] * 64 + c0));
            }
            #pragma unroll
            for (int q = 0; q < 8; q++) {
                float w = __expf(leaky02(ev[q] + edv) - m);
                s    += w;
                acc0 += w * hv[q].x;
                acc1 += w * hv[q].y;
            }
        }
        if (j + 4 <= cnt) {
            int sc[4]; float ev[4]; float2 hv[4];
            #pragma unroll
            for (int q = 0; q < 4; q++)
                sc[q] = __shfl_sync(0xffffffffu, myidx, j + q);
            #pragma unroll
            for (int q = 0; q < 4; q++) {
                ev[q] = __ldg(&g_es[sc[q] * 4 + hd]);
                hv[q] = __ldg((const float2*)(g_h + (size_t)sc[q] * 64 + c0));
            }
            #pragma unroll
            for (int q = 0; q < 4; q++) {
                float w = __expf(leaky02(ev[q] + edv) - m);
                s    += w;
                acc0 += w * hv[q].x;
                acc1 += w * hv[q].y;
            }
            j += 4;
        }
        for (; j < cnt; j++) {
            int sc = __shfl_sync(0xffffffffu, myidx, j);
            float  e  = __ldg(&g_es[sc * 4 + hd]);
            float2 hv = __ldg((const float2*)(g_h + (size_t)sc * 64 + c0));
            float w = __expf(leaky02(e + edv) - m);
            s    += w;
            acc0 += w * hv.x;
            acc1 += w * hv.y;
        }
    }
    float inv = 1.f / (s + 1e-16f);
    o0 = acc0 * inv + bias[c0];
    o1 = acc1 * inv + bias[c0 + 1];
}

// ------------------------------------------------------------------
// Aggregation layer 1 -> g_fb, one warp per node
// ------------------------------------------------------------------
__global__ __launch_bounds__(256) void k_aggregate(
    const float* __restrict__ bias, int layer)
{
    int t    = threadIdx.x;
    int lane = t & 31;
    int c0   = lane * 2;
    int hd   = lane >> 3;
    int n = blockIdx.x * 8 + (t >> 5);
    if (n >= NN) return;
    float o0, o1;
    agg_node(n, c0, hd, lane, layer, bias, o0, o1);
    size_t base = (size_t)n * 64 + c0;
    g_fb[base]     = o0;
    g_fb[base + 1] = o1;
}

// ------------------------------------------------------------------
// Aggregation (layer 2) fused with MLP + decoder + softmax epilogue.
// ------------------------------------------------------------------
__global__ __launch_bounds__(256) void k_agg_mlp(
    const float* __restrict__ bias, int layer,
    const float* __restrict__ lw1, const float* __restrict__ lb1,
    const float* __restrict__ lw2, const float* __restrict__ lb2,
    const float* __restrict__ dw,  const float* __restrict__ db,
    float* __restrict__ out)
{
    __shared__ float W1s[64 * 64];
    __shared__ float W2s[64 * 16];
    __shared__ float b1s[64], b2s[16], dws[64], dbs[4];
    __shared__ float t1s[8][64];
    __shared__ float t2s[8][16];
    __shared__ float lgs[8][4];
    int t = threadIdx.x;
    for (int i = t; i < 64 * 64; i += blockDim.x) W1s[i] = lw1[i];
    for (int i = t; i < 64 * 16; i += blockDim.x) W2s[i] = lw2[i];
    if (t < 64) b1s[t] = lb1[t];
    if (t < 16) b2s[t] = lb2[t];
    if (t < 64) dws[t] = dw[t];
    if (t < 4)  dbs[t] = db[t];
    __syncthreads();

    int lane = t & 31, w = t >> 5;
    int c0   = lane * 2;
    int hd   = lane >> 3;
    int n0 = blockIdx.x * 32 + w * 4;

    #pragma unroll 1
    for (int r = 0; r < 4; r++) {
        int n = n0 + r;
        if (n >= NN) break;

        float x0, x1;
        agg_node(n, c0, hd, lane, layer, bias, x0, x1);

        t1s[w][c0]     = x0;
        t1s[w][c0 + 1] = x1;
        __syncwarp();
        float a0 = b1s[c0], a1 = b1s[c0 + 1];
        #pragma unroll
        for (int k = 0; k < 64; k += 4) {
            float4 xv = *(const float4*)(&t1s[w][k]);
            float2 w0 = *(const float2*)(W1s + (k + 0) * 64 + c0);
            float2 w1 = *(const float2*)(W1s + (k + 1) * 64 + c0);
            float2 w2 = *(const float2*)(W1s + (k + 2) * 64 + c0);
            float2 w3 = *(const float2*)(W1s + (k + 3) * 64 + c0);
            a0 += xv.x * w0.x; a1 += xv.x * w0.y;
            a0 += xv.y * w1.x; a1 += xv.y * w1.y;
            a0 += xv.z * w2.x; a1 += xv.z * w2.y;
            a0 += xv.w * w3.x; a1 += xv.w * w3.y;
        }
        a0 = a0 > 0.f ? a0 : 0.f;
        a1 = a1 > 0.f ? a1 : 0.f;
        __syncwarp();
        t1s[w][c0]     = a0;
        t1s[w][c0 + 1] = a1;
        __syncwarp();
        if (lane < 16) {
            float acc = b2s[lane];
            #pragma unroll
            for (int k = 0; k < 64; k++) acc += t1s[w][k] * W2s[k * 16 + lane];
            t2s[w][lane] = acc;
        }
        __syncwarp();
        if (lane < 4) {
            float lg = dbs[lane];
            #pragma unroll
            for (int i = 0; i < 16; i++) lg += t2s[w][i] * dws[i * 4 + lane];
            lgs[w][lane] = lg;
        }
        __syncwarp();
        if (lane < 4) {
            float l0 = lgs[w][0], l1 = lgs[w][1], l2 = lgs[w][2], l3 = lgs[w][3];
            float mx = fmaxf(fmaxf(l0, l1), fmaxf(l2, l3));
            float e0 = __expf(l0 - mx), e1 = __expf(l1 - mx);
            float e2 = __expf(l2 - mx), e3 = __expf(l3 - mx);
            float den = e0 + e1 + e2 + e3;
            float mine = (lane == 0) ? e0 : (lane == 1) ? e1 : (lane == 2) ? e2 : e3;
            out[(size_t)n * 4 + lane] = mine / den;
        }
        __syncwarp();
    }
}

// ------------------------------------------------------------------
extern "C" void kernel_launch(void* const* d_in, const int* in_sizes, int n_in,
                              void* d_out, int out_size)
{
    const float* x   = (const float*)d_in[0];
    const int*   ei  = (const int*)  d_in[1];
    int E = in_sizes[1] / 2;
    const int* src = ei;
    const int* dst = ei + E;
    const float* W0  = (const float*)d_in[2];
    const float* as0 = (const float*)d_in[3];
    const float* ad0 = (const float*)d_in[4];
    const float* b0  = (const float*)d_in[5];
    const float* W1  = (const float*)d_in[6];
    const float* as1 = (const float*)d_in[7];
    const float* ad1 = (const float*)d_in[8];
    const float* b1  = (const float*)d_in[9];
    const float* W2  = (const float*)d_in[10];
    const float* as2 = (const float*)d_in[11];
    const float* ad2 = (const float*)d_in[12];
    const float* b2  = (const float*)d_in[13];
    const float* lw1 = (const float*)d_in[14];
    const float* lb1 = (const float*)d_in[15];
    const float* lw2 = (const float*)d_in[16];
    const float* lb2 = (const float*)d_in[17];
    const float* dw  = (const float*)d_in[18];
    const float* db  = (const float*)d_in[19];
    float* out = (float*)d_out;

    const int AGG_BLOCKS = (NN + 7) / 8;    // 1 node/warp, 8 warps/block
    const int TRF_BLOCKS = (NN + 31) / 32;  // 4 nodes/warp, 8 warps/block
    const int NT = 256;

    // CSR build (reused across all 3 GAT layers)
    k_init_deg<<<(NN + 255) / 256, 256>>>();
    k_hist<<<(E + 255) / 256, 256>>>(dst, E);
    k_scan1<<<SCAN_NB, 256>>>();
    k_scan2<<<1, 128>>>();
    k_scan3<<<SCAN_NB, SCAN_B>>>();
    k_fill<<<(E + NN + 255) / 256, 256>>>(src, dst, E);
    k_xmm<<<296, 256>>>(x);

    // GAT layer 0 (rank-1): aggregate x scalars -> g_s
    k_agg0<<<AGG_BLOCKS, NT>>>(x, W0, as0, ad0);
    // GAT layer 1: transform from S, aggregate -> g_fb
    k_transform_S<<<TRF_BLOCKS, NT>>>(W0, b0, W1, as1, ad1, 1);
    k_aggregate<<<AGG_BLOCKS, NT>>>(b1, 1);
    // GAT layer 2: transform from g_fb, fused aggregate + MLP -> out
    k_transform<<<TRF_BLOCKS, NT>>>(g_fb, W2, as2, ad2, 2);
    k_agg_mlp<<<TRF_BLOCKS, NT>>>(b2, 2, lw1, lb1, lw2, lb2, dw, db, out);
}

// round 8
// speedup vs baseline: 1.3157x; 1.3157x over previous
#include <cuda_runtime.h>

#define NN 100000
#define EMAX 1600000
#define SCAN_B 1024
#define SCAN_NB ((NN + SCAN_B - 1) / SCAN_B)   // 98

// ---- scratch (device globals; no runtime allocation allowed) ----
__device__ int      g_deg[NN];
__device__ int      g_off[NN + 1];
__device__ int      g_cur[NN];
__device__ int      g_csr[EMAX + NN];   // src node per CSR slot (sorted by dst)
__device__ float    g_h [NN * 64];      // transformed features for current layer
__device__ float    g_fa[NN * 64];      // ping
__device__ float    g_fb[NN * 64];      // pong
__device__ float    g_es[NN * 4];       // per-node source attention logits
__device__ float    g_ed[NN * 4];       // per-node dest attention logits
__device__ unsigned g_gmax[12];         // per-layer per-head global max of es
__device__ int      g_bsum[SCAN_NB];
__device__ int      g_boff[SCAN_NB];

__device__ __forceinline__ unsigned fenc(float f) {
    unsigned u = __float_as_uint(f);
    return u ^ ((u & 0x80000000u) ? 0xFFFFFFFFu : 0x80000000u);
}
__device__ __forceinline__ float fdec(unsigned e) {
    unsigned u = e ^ ((e & 0x80000000u) ? 0x80000000u : 0xFFFFFFFFu);
    return __uint_as_float(u);
}
__device__ __forceinline__ float leaky02(float e) {
    return (e > 0.f) ? e : 0.2f * e;
}

// ------------------------------------------------------------------
// CSR construction
// ------------------------------------------------------------------
__global__ void k_init_deg() {
    int i = blockIdx.x * blockDim.x + threadIdx.x;
    if (i < NN) g_deg[i] = 1;           // self-loop
    if (i < 12) g_gmax[i] = 0u;
}

__global__ void k_hist(const int* __restrict__ dst, int E) {
    int i = blockIdx.x * blockDim.x + threadIdx.x;
    if (i < E) atomicAdd(&g_deg[dst[i]], 1);
}

__global__ void k_scan1() {
    __shared__ int red[8];
    int b = blockIdx.x, t = threadIdx.x;
    int s = 0;
    #pragma unroll
    for (int j = 0; j < 4; j++) {
        int idx = b * SCAN_B + j * 256 + t;
        if (idx < NN) s += g_deg[idx];
    }
    #pragma unroll
    for (int o = 16; o >= 1; o >>= 1) s += __shfl_down_sync(0xffffffffu, s, o);
    if ((t & 31) == 0) red[t >> 5] = s;
    __syncthreads();
    if (t == 0) {
        int tot = 0;
        #pragma unroll
        for (int w = 0; w < 8; w++) tot += red[w];
        g_bsum[b] = tot;
    }
}

__global__ void k_scan2() {
    __shared__ int sh[128];
    int t = threadIdx.x;
    sh[t] = (t < SCAN_NB) ? g_bsum[t] : 0;
    __syncthreads();
    for (int o = 1; o < 128; o <<= 1) {
        int v = (t >= o) ? sh[t - o] : 0;
        __syncthreads();
        sh[t] += v;
        __syncthreads();
    }
    if (t < SCAN_NB) g_boff[t] = (t == 0) ? 0 : sh[t - 1];
    if (t == SCAN_NB - 1) g_off[NN] = sh[t];
}

__global__ void k_scan3() {
    __shared__ int sh[SCAN_B];
    int b = blockIdx.x, t = threadIdx.x;
    int i = b * SCAN_B + t;
    int v = (i < NN) ? g_deg[i] : 0;
    sh[t] = v;
    __syncthreads();
    for (int o = 1; o < SCAN_B; o <<= 1) {
        int u = (t >= o) ? sh[t - o] : 0;
        __syncthreads();
        sh[t] += u;
        __syncthreads();
    }
    if (i < NN) {
        int ex = sh[t] - v + g_boff[b];
        g_off[i] = ex;
        g_cur[i] = ex;
    }
}

__global__ void k_fill(const int* __restrict__ src, const int* __restrict__ dst, int E) {
    int i = blockIdx.x * blockDim.x + threadIdx.x;
    int tot = E + NN;
    if (i >= tot) return;
    int s, d;
    if (i < E) { s = src[i]; d = dst[i]; }
    else       { s = i - E; d = s; }
    int p = atomicAdd(&g_cur[d], 1);
    g_csr[p] = s;
}

// ------------------------------------------------------------------
// Node transform: 4 nodes per warp, hoisted W smem loads.
// xin_sel: 0 -> external ptr (Fin=1), 1 -> g_fa, 2 -> g_fb
// ------------------------------------------------------------------
__global__ __launch_bounds__(256) void k_transform(
    const float* __restrict__ xext, int xin_sel, int Fin,
    const float* __restrict__ Wg,
    const float* __restrict__ avs,
    const float* __restrict__ avd,
    int layer)
{
    __shared__ float Ws[64 * 64];
    __shared__ float As[64], Ad[64];
    __shared__ unsigned bmax[4];
    const float* xin = (xin_sel == 0) ? xext : (xin_sel == 1 ? g_fa : g_fb);
    int t = threadIdx.x;
    for (int i = t; i < Fin * 64; i += blockDim.x) Ws[i] = Wg[i];
    if (t < 64) { As[t] = avs[t]; Ad[t] = avd[t]; }
    if (t < 4)  bmax[t] = 0u;
    __syncthreads();

    int lane = t & 31;
    int c0   = lane * 2;
    int n0 = blockIdx.x * 32 + (t >> 5) * 4;
    int nv = NN - n0; if (nv > 4) nv = 4;

    float acc[4][2];
    #pragma unroll
    for (int r = 0; r < 4; r++) { acc[r][0] = 0.f; acc[r][1] = 0.f; }

    if (Fin == 1) {
        #pragma unroll
        for (int r = 0; r < 4; r++) {
            if (r < nv) {
                float xv = __ldg(xin + n0 + r);
                acc[r][0] = xv * Ws[c0];
                acc[r][1] = xv * Ws[c0 + 1];
            }
        }
    } else {
        const float* x0p = xin + (size_t)n0 * 64;
        #pragma unroll
        for (int k = 0; k < 64; k += 4) {
            float2 w0 = *(const float2*)(Ws + (k + 0) * 64 + c0);
            float2 w1 = *(const float2*)(Ws + (k + 1) * 64 + c0);
            float2 w2 = *(const float2*)(Ws + (k + 2) * 64 + c0);
            float2 w3 = *(const float2*)(Ws + (k + 3) * 64 + c0);
            #pragma unroll
            for (int r = 0; r < 4; r++) {
                if (r < nv) {
                    float4 xv = __ldg((const float4*)(x0p + r * 64 + k));
                    acc[r][0] += xv.x * w0.x; acc[r][1] += xv.x * w0.y;
                    acc[r][0] += xv.y * w1.x; acc[r][1] += xv.y * w1.y;
                    acc[r][0] += xv.z * w2.x; acc[r][1] += xv.z * w2.y;
                    acc[r][0] += xv.w * w3.x; acc[r][1] += xv.w * w3.y;
                }
            }
        }
    }

    #pragma unroll
    for (int r = 0; r < 4; r++) {
        if (r >= nv) break;
        int n = n0 + r;
        float a0 = acc[r][0], a1 = acc[r][1];
        size_t base = (size_t)n * 64 + c0;
        g_h[base]     = a0;
        g_h[base + 1] = a1;
        float ps = a0 * As[c0] + a1 * As[c0 + 1];
        float pd = a0 * Ad[c0] + a1 * Ad[c0 + 1];
        #pragma unroll
        for (int o = 4; o >= 1; o >>= 1) {
            ps += __shfl_down_sync(0xffffffffu, ps, o);
            pd += __shfl_down_sync(0xffffffffu, pd, o);
        }
        if ((lane & 7) == 0) {
            int hd = lane >> 3;
            g_es[n * 4 + hd] = ps;
            g_ed[n * 4 + hd] = pd;
            atomicMax(&bmax[hd], fenc(ps));
        }
    }
    __syncthreads();
    if (t < 4) atomicMax(&g_gmax[layer * 4 + t], bmax[t]);
}

// ------------------------------------------------------------------
// Half-warp (16-lane) single-pass softmax aggregation. Lane l owns
// channels 4l..4l+3 (float4 row loads), head = l>>2. Two nodes per
// warp -> two independent load chains (2x MLP vs warp-per-node).
// ------------------------------------------------------------------
__device__ __forceinline__ float4 agg_node16(
    int n, int l16, int hb, unsigned hmask, int layer,
    const float* __restrict__ bias)
{
    int hd = l16 >> 2;
    int q0 = l16 * 4;
    int beg = __ldg(&g_off[n]), end = __ldg(&g_off[n + 1]);
    float edv = __ldg(&g_ed[n * 4 + hd]);
    float m = leaky02(fdec(g_gmax[layer * 4 + hd]) + edv);

    float s = 0.f;
    float a0 = 0.f, a1 = 0.f, a2 = 0.f, a3 = 0.f;
    for (int base = beg; base < end; base += 16) {
        int rem = end - base;
        int cnt = rem < 16 ? rem : 16;
        int safel = l16 < rem ? l16 : 0;
        int myidx = __ldg(&g_csr[base + safel]);   // coalesced 64B, 16 edges
        int j = 0;
        for (; j + 8 <= cnt; j += 8) {
            int sc[8]; float ev[8]; float4 hv[8];
            #pragma unroll
            for (int q = 0; q < 8; q++)
                sc[q] = __shfl_sync(hmask, myidx, hb + j + q);
            #pragma unroll
            for (int q = 0; q < 8; q++) {
                ev[q] = __ldg(&g_es[sc[q] * 4 + hd]);
                hv[q] = __ldg((const float4*)(g_h + (size_t)sc[q] * 64 + q0));
            }
            #pragma unroll
            for (int q = 0; q < 8; q++) {
                float w = __expf(leaky02(ev[q] + edv) - m);
                s  += w;
                a0 += w * hv[q].x; a1 += w * hv[q].y;
                a2 += w * hv[q].z; a3 += w * hv[q].w;
            }
        }
        if (j + 4 <= cnt) {
            int sc[4]; float ev[4]; float4 hv[4];
            #pragma unroll
            for (int q = 0; q < 4; q++)
                sc[q] = __shfl_sync(hmask, myidx, hb + j + q);
            #pragma unroll
            for (int q = 0; q < 4; q++) {
                ev[q] = __ldg(&g_es[sc[q] * 4 + hd]);
                hv[q] = __ldg((const float4*)(g_h + (size_t)sc[q] * 64 + q0));
            }
            #pragma unroll
            for (int q = 0; q < 4; q++) {
                float w = __expf(leaky02(ev[q] + edv) - m);
                s  += w;
                a0 += w * hv[q].x; a1 += w * hv[q].y;
                a2 += w * hv[q].z; a3 += w * hv[q].w;
            }
            j += 4;
        }
        for (; j < cnt; j++) {
            int sc = __shfl_sync(hmask, myidx, hb + j);
            float  e  = __ldg(&g_es[sc * 4 + hd]);
            float4 hv = __ldg((const float4*)(g_h + (size_t)sc * 64 + q0));
            float w = __expf(leaky02(e + edv) - m);
            s  += w;
            a0 += w * hv.x; a1 += w * hv.y;
            a2 += w * hv.z; a3 += w * hv.w;
        }
    }
    float inv = 1.f / (s + 1e-16f);
    float4 bv = __ldg((const float4*)(bias + q0));
    float4 o;
    o.x = a0 * inv + bv.x;
    o.y = a1 * inv + bv.y;
    o.z = a2 * inv + bv.z;
    o.w = a3 * inv + bv.w;
    return o;
}

// ------------------------------------------------------------------
// Aggregation -> feature buffer (layers 0 and 1): half-warp per node
// ------------------------------------------------------------------
__global__ __launch_bounds__(256) void k_aggregate(
    const float* __restrict__ bias, int out_sel, int layer)
{
    float* xout = (out_sel == 1) ? g_fa : g_fb;
    int t    = threadIdx.x;
    int lane = t & 31;
    int l16  = lane & 15;
    int hb   = lane & 16;                 // 0 or 16 (half base within warp)
    unsigned hmask = 0xFFFFu << hb;
    int n = blockIdx.x * 16 + (t >> 4);
    if (n >= NN) return;
    float4 o = agg_node16(n, l16, hb, hmask, layer, bias);
    *(float4*)(xout + (size_t)n * 64 + l16 * 4) = o;
}

// ------------------------------------------------------------------
// 32-lane aggregation core (kept for the fused agg+MLP kernel).
// ------------------------------------------------------------------
__device__ __forceinline__ void agg_node(
    int n, int c0, int hd, int lane, int layer, const float* __restrict__ bias,
    float& o0, float& o1)
{
    int beg = __ldg(&g_off[n]), end = __ldg(&g_off[n + 1]);
    float edv = __ldg(&g_ed[n * 4 + hd]);
    float m = leaky02(fdec(g_gmax[layer * 4 + hd]) + edv);

    float s = 0.f, acc0 = 0.f, acc1 = 0.f;
    for (int base = beg; base < end; base += 32) {
        int rem = end - base;
        int cnt = rem < 32 ? rem : 32;
        int safel = lane < rem ? lane : 0;
        int myidx = __ldg(&g_csr[base + safel]);
        int j = 0;
        for (; j + 8 <= cnt; j += 8) {
            int sc[8]; float ev[8]; float2 hv[8];
            #pragma unroll
            for (int q = 0; q < 8; q++)
                sc[q] = __shfl_sync(0xffffffffu, myidx, j + q);
            #pragma unroll
            for (int q = 0; q < 8; q++) {
                ev[q] = __ldg(&g_es[sc[q] * 4 + hd]);
                hv[q] = __ldg((const float2*)(g_h + (size_t)sc[q] * 64 + c0));
            }
            #pragma unroll
            for (int q = 0; q < 8; q++) {
                float w = __expf(leaky02(ev[q] + edv) - m);
                s    += w;
                acc0 += w * hv[q].x;
                acc1 += w * hv[q].y;
            }
        }
        if (j + 4 <= cnt) {
            int sc[4]; float ev[4]; float2 hv[4];
            #pragma unroll
            for (int q = 0; q < 4; q++)
                sc[q] = __shfl_sync(0xffffffffu, myidx, j + q);
            #pragma unroll
            for (int q = 0; q < 4; q++) {
                ev[q] = __ldg(&g_es[sc[q] * 4 + hd]);
                hv[q] = __ldg((const float2*)(g_h + (size_t)sc[q] * 64 + c0));
            }
            #pragma unroll
            for (int q = 0; q < 4; q++) {
                float w = __expf(leaky02(ev[q] + edv) - m);
                s    += w;
                acc0 += w * hv[q].x;
                acc1 += w * hv[q].y;
            }
            j += 4;
        }
        for (; j < cnt; j++) {
            int sc = __shfl_sync(0xffffffffu, myidx, j);
            float  e  = __ldg(&g_es[sc * 4 + hd]);
            float2 hv = __ldg((const float2*)(g_h + (size_t)sc * 64 + c0));
            float w = __expf(leaky02(e + edv) - m);
            s    += w;
            acc0 += w * hv.x;
            acc1 += w * hv.y;
        }
    }
    float inv = 1.f / (s + 1e-16f);
    o0 = acc0 * inv + bias[c0];
    o1 = acc1 * inv + bias[c0 + 1];
}

// ------------------------------------------------------------------
// Aggregation (layer 2) fused with MLP + decoder + softmax epilogue.
// ------------------------------------------------------------------
__global__ __launch_bounds__(256) void k_agg_mlp(
    const float* __restrict__ bias, int layer,
    const float* __restrict__ lw1, const float* __restrict__ lb1,
    const float* __restrict__ lw2, const float* __restrict__ lb2,
    const float* __restrict__ dw,  const float* __restrict__ db,
    float* __restrict__ out)
{
    __shared__ float W1s[64 * 64];
    __shared__ float W2s[64 * 16];
    __shared__ float b1s[64], b2s[16], dws[64], dbs[4];
    __shared__ float t1s[8][64];
    __shared__ float t2s[8][16];
    __shared__ float lgs[8][4];
    int t = threadIdx.x;
    for (int i = t; i < 64 * 64; i += blockDim.x) W1s[i] = lw1[i];
    for (int i = t; i < 64 * 16; i += blockDim.x) W2s[i] = lw2[i];
    if (t < 64) b1s[t] = lb1[t];
    if (t < 16) b2s[t] = lb2[t];
    if (t < 64) dws[t] = dw[t];
    if (t < 4)  dbs[t] = db[t];
    __syncthreads();

    int lane = t & 31, w = t >> 5;
    int c0   = lane * 2;
    int hd   = lane >> 3;
    int n0 = blockIdx.x * 32 + w * 4;

    #pragma unroll 1
    for (int r = 0; r < 4; r++) {
        int n = n0 + r;
        if (n >= NN) break;

        float x0, x1;
        agg_node(n, c0, hd, lane, layer, bias, x0, x1);

        t1s[w][c0]     = x0;
        t1s[w][c0 + 1] = x1;
        __syncwarp();
        float a0 = b1s[c0], a1 = b1s[c0 + 1];
        #pragma unroll
        for (int k = 0; k < 64; k += 4) {
            float4 xv = *(const float4*)(&t1s[w][k]);
            float2 w0 = *(const float2*)(W1s + (k + 0) * 64 + c0);
            float2 w1 = *(const float2*)(W1s + (k + 1) * 64 + c0);
            float2 w2 = *(const float2*)(W1s + (k + 2) * 64 + c0);
            float2 w3 = *(const float2*)(W1s + (k + 3) * 64 + c0);
            a0 += xv.x * w0.x; a1 += xv.x * w0.y;
            a0 += xv.y * w1.x; a1 += xv.y * w1.y;
            a0 += xv.z * w2.x; a1 += xv.z * w2.y;
            a0 += xv.w * w3.x; a1 += xv.w * w3.y;
        }
        a0 = a0 > 0.f ? a0 : 0.f;
        a1 = a1 > 0.f ? a1 : 0.f;
        __syncwarp();
        t1s[w][c0]     = a0;
        t1s[w][c0 + 1] = a1;
        __syncwarp();
        if (lane < 16) {
            float acc = b2s[lane];
            #pragma unroll
            for (int k = 0; k < 64; k++) acc += t1s[w][k] * W2s[k * 16 + lane];
            t2s[w][lane] = acc;
        }
        __syncwarp();
        if (lane < 4) {
            float lg = dbs[lane];
            #pragma unroll
            for (int i = 0; i < 16; i++) lg += t2s[w][i] * dws[i * 4 + lane];
            lgs[w][lane] = lg;
        }
        __syncwarp();
        if (lane < 4) {
            float l0 = lgs[w][0], l1 = lgs[w][1], l2 = lgs[w][2], l3 = lgs[w][3];
            float mx = fmaxf(fmaxf(l0, l1), fmaxf(l2, l3));
            float e0 = __expf(l0 - mx), e1 = __expf(l1 - mx);
            float e2 = __expf(l2 - mx), e3 = __expf(l3 - mx);
            float den = e0 + e1 + e2 + e3;
            float mine = (lane == 0) ? e0 : (lane == 1) ? e1 : (lane == 2) ? e2 : e3;
            out[(size_t)n * 4 + lane] = mine / den;
        }
        __syncwarp();
    }
}

// ------------------------------------------------------------------
extern "C" void kernel_launch(void* const* d_in, const int* in_sizes, int n_in,
                              void* d_out, int out_size)
{
    const float* x   = (const float*)d_in[0];
    const int*   ei  = (const int*)  d_in[1];
    int E = in_sizes[1] / 2;
    const int* src = ei;
    const int* dst = ei + E;
    const float* W0  = (const float*)d_in[2];
    const float* as0 = (const float*)d_in[3];
    const float* ad0 = (const float*)d_in[4];
    const float* b0  = (const float*)d_in[5];
    const float* W1  = (const float*)d_in[6];
    const float* as1 = (const float*)d_in[7];
    const float* ad1 = (const float*)d_in[8];
    const float* b1  = (const float*)d_in[9];
    const float* W2  = (const float*)d_in[10];
    const float* as2 = (const float*)d_in[11];
    const float* ad2 = (const float*)d_in[12];
    const float* b2  = (const float*)d_in[13];
    const float* lw1 = (const float*)d_in[14];
    const float* lb1 = (const float*)d_in[15];
    const float* lw2 = (const float*)d_in[16];
    const float* lb2 = (const float*)d_in[17];
    const float* dw  = (const float*)d_in[18];
    const float* db  = (const float*)d_in[19];
    float* out = (float*)d_out;

    const int AGG16_BLOCKS = (NN + 15) / 16;  // half-warp per node
    const int TRF_BLOCKS   = (NN + 31) / 32;  // 4 nodes/warp, 8 warps/block
    const int NT = 256;

    // CSR build (reused across all 3 GAT layers)
    k_init_deg<<<(NN + 255) / 256, 256>>>();
    k_hist<<<(E + 255) / 256, 256>>>(dst, E);
    k_scan1<<<SCAN_NB, 256>>>();
    k_scan2<<<1, 128>>>();
    k_scan3<<<SCAN_NB, SCAN_B>>>();
    k_fill<<<(E + NN + 255) / 256, 256>>>(src, dst, E);

    // GAT layer 0 (Fin=1): out -> g_fa
    k_transform<<<TRF_BLOCKS, NT>>>(x, 0, 1, W0, as0, ad0, 0);
    k_aggregate<<<AGG16_BLOCKS, NT>>>(b0, 1, 0);
    // GAT layer 1 (Fin=64): in g_fa, out -> g_fb
    k_transform<<<TRF_BLOCKS, NT>>>(nullptr, 1, 64, W1, as1, ad1, 1);
    k_aggregate<<<AGG16_BLOCKS, NT>>>(b1, 2, 1);
    // GAT layer 2 (Fin=64): in g_fb, fused aggregate + MLP + decoder -> out
    k_transform<<<TRF_BLOCKS, NT>>>(nullptr, 2, 64, W2, as2, ad2, 2);
    k_agg_mlp<<<TRF_BLOCKS, NT>>>(b2, 2, lw1, lb1, lw2, lb2, dw, db, out);
}

// round 9
// speedup vs baseline: 1.3985x; 1.0629x over previous
#include <cuda_runtime.h>

#define NN 100000
#define EMAX 1600000
#define SCAN_B 1024
#define SCAN_NB ((NN + SCAN_B - 1) / SCAN_B)   // 98

// ---- scratch (device globals; no runtime allocation allowed) ----
__device__ int      g_deg[NN];
__device__ int      g_off[NN + 1];
__device__ int      g_cur[NN];
__device__ int      g_csr[EMAX + NN];   // src node per CSR slot (sorted by dst)
__device__ float    g_h [NN * 64];      // transformed features for current layer
__device__ float    g_fa[NN * 64];      // ping
__device__ float    g_fb[NN * 64];      // pong
__device__ float    g_es[NN * 4];       // per-node source attention logits
__device__ float    g_ed[NN * 4];       // per-node dest attention logits
__device__ unsigned g_gmax[12];         // per-layer per-head global max of es
__device__ int      g_bsum[SCAN_NB];
__device__ int      g_boff[SCAN_NB];

__device__ __forceinline__ unsigned fenc(float f) {
    unsigned u = __float_as_uint(f);
    return u ^ ((u & 0x80000000u) ? 0xFFFFFFFFu : 0x80000000u);
}
__device__ __forceinline__ float fdec(unsigned e) {
    unsigned u = e ^ ((e & 0x80000000u) ? 0x80000000u : 0xFFFFFFFFu);
    return __uint_as_float(u);
}
__device__ __forceinline__ float leaky02(float e) {
    return (e > 0.f) ? e : 0.2f * e;
}

// ------------------------------------------------------------------
// CSR construction
// ------------------------------------------------------------------
__global__ void k_init_deg() {
    int i = blockIdx.x * blockDim.x + threadIdx.x;
    if (i < NN) g_deg[i] = 1;           // self-loop
    if (i < 12) g_gmax[i] = 0u;
}

__global__ void k_hist(const int* __restrict__ dst, int E) {
    int i = blockIdx.x * blockDim.x + threadIdx.x;
    if (i < E) atomicAdd(&g_deg[dst[i]], 1);
}

__global__ void k_scan1() {
    __shared__ int red[8];
    int b = blockIdx.x, t = threadIdx.x;
    int s = 0;
    #pragma unroll
    for (int j = 0; j < 4; j++) {
        int idx = b * SCAN_B + j * 256 + t;
        if (idx < NN) s += g_deg[idx];
    }
    #pragma unroll
    for (int o = 16; o >= 1; o >>= 1) s += __shfl_down_sync(0xffffffffu, s, o);
    if ((t & 31) == 0) red[t >> 5] = s;
    __syncthreads();
    if (t == 0) {
        int tot = 0;
        #pragma unroll
        for (int w = 0; w < 8; w++) tot += red[w];
        g_bsum[b] = tot;
    }
}

__global__ void k_scan2() {
    __shared__ int sh[128];
    int t = threadIdx.x;
    sh[t] = (t < SCAN_NB) ? g_bsum[t] : 0;
    __syncthreads();
    for (int o = 1; o < 128; o <<= 1) {
        int v = (t >= o) ? sh[t - o] : 0;
        __syncthreads();
        sh[t] += v;
        __syncthreads();
    }
    if (t < SCAN_NB) g_boff[t] = (t == 0) ? 0 : sh[t - 1];
    if (t == SCAN_NB - 1) g_off[NN] = sh[t];
}

__global__ void k_scan3() {
    __shared__ int sh[SCAN_B];
    int b = blockIdx.x, t = threadIdx.x;
    int i = b * SCAN_B + t;
    int v = (i < NN) ? g_deg[i] : 0;
    sh[t] = v;
    __syncthreads();
    for (int o = 1; o < SCAN_B; o <<= 1) {
        int u = (t >= o) ? sh[t - o] : 0;
        __syncthreads();
        sh[t] += u;
        __syncthreads();
    }
    if (i < NN) {
        int ex = sh[t] - v + g_boff[b];
        g_off[i] = ex;
        g_cur[i] = ex;
    }
}

__global__ void k_fill(const int* __restrict__ src, const int* __restrict__ dst, int E) {
    int i = blockIdx.x * blockDim.x + threadIdx.x;
    int tot = E + NN;
    if (i >= tot) return;
    int s, d;
    if (i < E) { s = src[i]; d = dst[i]; }
    else       { s = i - E; d = s; }
    int p = atomicAdd(&g_cur[d], 1);
    g_csr[p] = s;
}

// ------------------------------------------------------------------
// Node transform: 4 nodes per warp, hoisted W smem loads.
// xin_sel: 0 -> external ptr (Fin=1), 1 -> g_fa, 2 -> g_fb
// ------------------------------------------------------------------
__global__ __launch_bounds__(256) void k_transform(
    const float* __restrict__ xext, int xin_sel, int Fin,
    const float* __restrict__ Wg,
    const float* __restrict__ avs,
    const float* __restrict__ avd,
    int layer)
{
    __shared__ float Ws[64 * 64];
    __shared__ float As[64], Ad[64];
    __shared__ unsigned bmax[4];
    const float* xin = (xin_sel == 0) ? xext : (xin_sel == 1 ? g_fa : g_fb);
    int t = threadIdx.x;
    for (int i = t; i < Fin * 64; i += blockDim.x) Ws[i] = Wg[i];
    if (t < 64) { As[t] = avs[t]; Ad[t] = avd[t]; }
    if (t < 4)  bmax[t] = 0u;
    __syncthreads();

    int lane = t & 31;
    int c0   = lane * 2;
    int n0 = blockIdx.x * 32 + (t >> 5) * 4;
    int nv = NN - n0; if (nv > 4) nv = 4;

    float acc[4][2];
    #pragma unroll
    for (int r = 0; r < 4; r++) { acc[r][0] = 0.f; acc[r][1] = 0.f; }

    if (Fin == 1) {
        #pragma unroll
        for (int r = 0; r < 4; r++) {
            if (r < nv) {
                float xv = __ldg(xin + n0 + r);
                acc[r][0] = xv * Ws[c0];
                acc[r][1] = xv * Ws[c0 + 1];
            }
        }
    } else {
        const float* x0p = xin + (size_t)n0 * 64;
        #pragma unroll
        for (int k = 0; k < 64; k += 4) {
            float2 w0 = *(const float2*)(Ws + (k + 0) * 64 + c0);
            float2 w1 = *(const float2*)(Ws + (k + 1) * 64 + c0);
            float2 w2 = *(const float2*)(Ws + (k + 2) * 64 + c0);
            float2 w3 = *(const float2*)(Ws + (k + 3) * 64 + c0);
            #pragma unroll
            for (int r = 0; r < 4; r++) {
                if (r < nv) {
                    float4 xv = __ldg((const float4*)(x0p + r * 64 + k));
                    acc[r][0] += xv.x * w0.x; acc[r][1] += xv.x * w0.y;
                    acc[r][0] += xv.y * w1.x; acc[r][1] += xv.y * w1.y;
                    acc[r][0] += xv.z * w2.x; acc[r][1] += xv.z * w2.y;
                    acc[r][0] += xv.w * w3.x; acc[r][1] += xv.w * w3.y;
                }
            }
        }
    }

    #pragma unroll
    for (int r = 0; r < 4; r++) {
        if (r >= nv) break;
        int n = n0 + r;
        float a0 = acc[r][0], a1 = acc[r][1];
        size_t base = (size_t)n * 64 + c0;
        g_h[base]     = a0;
        g_h[base + 1] = a1;
        float ps = a0 * As[c0] + a1 * As[c0 + 1];
        float pd = a0 * Ad[c0] + a1 * Ad[c0 + 1];
        #pragma unroll
        for (int o = 4; o >= 1; o >>= 1) {
            ps += __shfl_down_sync(0xffffffffu, ps, o);
            pd += __shfl_down_sync(0xffffffffu, pd, o);
        }
        if ((lane & 7) == 0) {
            int hd = lane >> 3;
            g_es[n * 4 + hd] = ps;
            g_ed[n * 4 + hd] = pd;
            atomicMax(&bmax[hd], fenc(ps));
        }
    }
    __syncthreads();
    if (t < 4) atomicMax(&g_gmax[layer * 4 + t], bmax[t]);
}

// ------------------------------------------------------------------
// Half-warp (16-lane) single-pass softmax aggregation. Lane l owns
// channels 4l..4l+3 (float4 row loads), head = l>>2.
// ------------------------------------------------------------------
__device__ __forceinline__ float4 agg_node16(
    int n, int l16, int hb, unsigned hmask, int layer,
    const float* __restrict__ bias)
{
    int hd = l16 >> 2;
    int q0 = l16 * 4;
    int beg = __ldg(&g_off[n]), end = __ldg(&g_off[n + 1]);
    float edv = __ldg(&g_ed[n * 4 + hd]);
    float m = leaky02(fdec(g_gmax[layer * 4 + hd]) + edv);

    float s = 0.f;
    float a0 = 0.f, a1 = 0.f, a2 = 0.f, a3 = 0.f;
    for (int base = beg; base < end; base += 16) {
        int rem = end - base;
        int cnt = rem < 16 ? rem : 16;
        int safel = l16 < rem ? l16 : 0;
        int myidx = __ldg(&g_csr[base + safel]);   // coalesced 64B, 16 edges
        int j = 0;
        for (; j + 8 <= cnt; j += 8) {
            int sc[8]; float ev[8]; float4 hv[8];
            #pragma unroll
            for (int q = 0; q < 8; q++)
                sc[q] = __shfl_sync(hmask, myidx, hb + j + q);
            #pragma unroll
            for (int q = 0; q < 8; q++) {
                ev[q] = __ldg(&g_es[sc[q] * 4 + hd]);
                hv[q] = __ldg((const float4*)(g_h + (size_t)sc[q] * 64 + q0));
            }
            #pragma unroll
            for (int q = 0; q < 8; q++) {
                float w = __expf(leaky02(ev[q] + edv) - m);
                s  += w;
                a0 += w * hv[q].x; a1 += w * hv[q].y;
                a2 += w * hv[q].z; a3 += w * hv[q].w;
            }
        }
        if (j + 4 <= cnt) {
            int sc[4]; float ev[4]; float4 hv[4];
            #pragma unroll
            for (int q = 0; q < 4; q++)
                sc[q] = __shfl_sync(hmask, myidx, hb + j + q);
            #pragma unroll
            for (int q = 0; q < 4; q++) {
                ev[q] = __ldg(&g_es[sc[q] * 4 + hd]);
                hv[q] = __ldg((const float4*)(g_h + (size_t)sc[q] * 64 + q0));
            }
            #pragma unroll
            for (int q = 0; q < 4; q++) {
                float w = __expf(leaky02(ev[q] + edv) - m);
                s  += w;
                a0 += w * hv[q].x; a1 += w * hv[q].y;
                a2 += w * hv[q].z; a3 += w * hv[q].w;
            }
            j += 4;
        }
        for (; j < cnt; j++) {
            int sc = __shfl_sync(hmask, myidx, hb + j);
            float  e  = __ldg(&g_es[sc * 4 + hd]);
            float4 hv = __ldg((const float4*)(g_h + (size_t)sc * 64 + q0));
            float w = __expf(leaky02(e + edv) - m);
            s  += w;
            a0 += w * hv.x; a1 += w * hv.y;
            a2 += w * hv.z; a3 += w * hv.w;
        }
    }
    float inv = 1.f / (s + 1e-16f);
    float4 bv = __ldg((const float4*)(bias + q0));
    float4 o;
    o.x = a0 * inv + bv.x;
    o.y = a1 * inv + bv.y;
    o.z = a2 * inv + bv.z;
    o.w = a3 * inv + bv.w;
    return o;
}

// ------------------------------------------------------------------
// Aggregation -> feature buffer (layers 0 and 1): half-warp per node
// ------------------------------------------------------------------
__global__ __launch_bounds__(256) void k_aggregate(
    const float* __restrict__ bias, int out_sel, int layer)
{
    float* xout = (out_sel == 1) ? g_fa : g_fb;
    int t    = threadIdx.x;
    int lane = t & 31;
    int l16  = lane & 15;
    int hb   = lane & 16;
    unsigned hmask = 0xFFFFu << hb;
    int n = blockIdx.x * 16 + (t >> 4);
    if (n >= NN) return;
    float4 o = agg_node16(n, l16, hb, hmask, layer, bias);
    *(float4*)(xout + (size_t)n * 64 + l16 * 4) = o;
}

// ------------------------------------------------------------------
// Layer-2 aggregate fused with MLP + decoder + softmax.
// Half-warp per node: 16 nodes per 256-thread block, no serial loop.
// t1s rows padded to 68 floats (16B-aligned, kills cross-half 2-way
// bank conflict on the broadcast row reads).
// ------------------------------------------------------------------
__global__ __launch_bounds__(256) void k_agg_mlp(
    const float* __restrict__ bias, int layer,
    const float* __restrict__ lw1, const float* __restrict__ lb1,
    const float* __restrict__ lw2, const float* __restrict__ lb2,
    const float* __restrict__ dw,  const float* __restrict__ db,
    float* __restrict__ out)
{
    __shared__ float W1s[64 * 64];
    __shared__ float W2s[64 * 16];
    __shared__ float b1s[64], b2s[16], dws[64], dbs[4];
    __shared__ float t1s[16][68];
    __shared__ float t2s[16][16];
    __shared__ float lgs[16][4];
    int t = threadIdx.x;
    for (int i = t; i < 64 * 64; i += blockDim.x) W1s[i] = lw1[i];
    for (int i = t; i < 64 * 16; i += blockDim.x) W2s[i] = lw2[i];
    if (t < 64) b1s[t] = lb1[t];
    if (t < 16) b2s[t] = lb2[t];
    if (t < 64) dws[t] = dw[t];
    if (t < 4)  dbs[t] = db[t];
    __syncthreads();

    int lane = t & 31;
    int l16  = lane & 15;
    int hb   = lane & 16;
    unsigned hmask = 0xFFFFu << hb;
    int hid  = t >> 4;                  // half-warp id within block (0..15)
    int q0   = l16 * 4;
    int n = blockIdx.x * 16 + hid;
    if (n >= NN) return;

    // ---- layer-2 aggregation (half-warp) ----
    float4 xr = agg_node16(n, l16, hb, hmask, layer, bias);
    *(float4*)(&t1s[hid][q0]) = xr;
    __syncwarp();

    // ---- Linear(64,64) + ReLU: lane owns 4 output channels ----
    float a0 = b1s[q0], a1 = b1s[q0 + 1], a2 = b1s[q0 + 2], a3 = b1s[q0 + 3];
    #pragma unroll
    for (int k = 0; k < 64; k++) {
        float xv = t1s[hid][k];
        float4 wv = *(const float4*)(W1s + k * 64 + q0);
        a0 += xv * wv.x; a1 += xv * wv.y;
        a2 += xv * wv.z; a3 += xv * wv.w;
    }
    a0 = a0 > 0.f ? a0 : 0.f;
    a1 = a1 > 0.f ? a1 : 0.f;
    a2 = a2 > 0.f ? a2 : 0.f;
    a3 = a3 > 0.f ? a3 : 0.f;
    __syncwarp();
    t1s[hid][q0]     = a0;
    t1s[hid][q0 + 1] = a1;
    t1s[hid][q0 + 2] = a2;
    t1s[hid][q0 + 3] = a3;
    __syncwarp();

    // ---- Linear(64,16): lane l16 computes output channel l16 ----
    {
        float acc = b2s[l16];
        #pragma unroll
        for (int k = 0; k < 64; k++) acc += t1s[hid][k] * W2s[k * 16 + l16];
        t2s[hid][l16] = acc;
    }
    __syncwarp();

    // ---- decoder Linear(16,4) ----
    if (l16 < 4) {
        float lg = dbs[l16];
        #pragma unroll
        for (int i = 0; i < 16; i++) lg += t2s[hid][i] * dws[i * 4 + l16];
        lgs[hid][l16] = lg;
    }
    __syncwarp();

    // ---- softmax over 4 logits ----
    if (l16 < 4) {
        float l0 = lgs[hid][0], l1 = lgs[hid][1], l2 = lgs[hid][2], l3 = lgs[hid][3];
        float mx = fmaxf(fmaxf(l0, l1), fmaxf(l2, l3));
        float e0 = __expf(l0 - mx), e1 = __expf(l1 - mx);
        float e2 = __expf(l2 - mx), e3 = __expf(l3 - mx);
        float den = e0 + e1 + e2 + e3;
        float mine = (l16 == 0) ? e0 : (l16 == 1) ? e1 : (l16 == 2) ? e2 : e3;
        out[(size_t)n * 4 + l16] = mine / den;
    }
}

// ------------------------------------------------------------------
extern "C" void kernel_launch(void* const* d_in, const int* in_sizes, int n_in,
                              void* d_out, int out_size)
{
    const float* x   = (const float*)d_in[0];
    const int*   ei  = (const int*)  d_in[1];
    int E = in_sizes[1] / 2;
    const int* src = ei;
    const int* dst = ei + E;
    const float* W0  = (const float*)d_in[2];
    const float* as0 = (const float*)d_in[3];
    const float* ad0 = (const float*)d_in[4];
    const float* b0  = (const float*)d_in[5];
    const float* W1  = (const float*)d_in[6];
    const float* as1 = (const float*)d_in[7];
    const float* ad1 = (const float*)d_in[8];
    const float* b1  = (const float*)d_in[9];
    const float* W2  = (const float*)d_in[10];
    const float* as2 = (const float*)d_in[11];
    const float* ad2 = (const float*)d_in[12];
    const float* b2  = (const float*)d_in[13];
    const float* lw1 = (const float*)d_in[14];
    const float* lb1 = (const float*)d_in[15];
    const float* lw2 = (const float*)d_in[16];
    const float* lb2 = (const float*)d_in[17];
    const float* dw  = (const float*)d_in[18];
    const float* db  = (const float*)d_in[19];
    float* out = (float*)d_out;

    const int AGG16_BLOCKS = (NN + 15) / 16;  // half-warp per node
    const int TRF_BLOCKS   = (NN + 31) / 32;  // 4 nodes/warp, 8 warps/block
    const int NT = 256;

    // CSR build (reused across all 3 GAT layers)
    k_init_deg<<<(NN + 255) / 256, 256>>>();
    k_hist<<<(E + 255) / 256, 256>>>(dst, E);
    k_scan1<<<SCAN_NB, 256>>>();
    k_scan2<<<1, 128>>>();
    k_scan3<<<SCAN_NB, SCAN_B>>>();
    k_fill<<<(E + NN + 255) / 256, 256>>>(src, dst, E);

    // GAT layer 0 (Fin=1): out -> g_fa
    k_transform<<<TRF_BLOCKS, NT>>>(x, 0, 1, W0, as0, ad0, 0);
    k_aggregate<<<AGG16_BLOCKS, NT>>>(b0, 1, 0);
    // GAT layer 1 (Fin=64): in g_fa, out -> g_fb
    k_transform<<<TRF_BLOCKS, NT>>>(nullptr, 1, 64, W1, as1, ad1, 1);
    k_aggregate<<<AGG16_BLOCKS, NT>>>(b1, 2, 1);
    // GAT layer 2 (Fin=64): in g_fb, fused aggregate + MLP + decoder -> out
    k_transform<<<TRF_BLOCKS, NT>>>(nullptr, 2, 64, W2, as2, ad2, 2);
    k_agg_mlp<<<AGG16_BLOCKS, NT>>>(b2, 2, lw1, lb1, lw2, lb2, dw, db, out);
}